// round 15
// baseline (speedup 1.0000x reference)
#include <cuda_runtime.h>
#include <cuda_bf16.h>
#include <cstdint>

// Problem constants
#define NIMG 8
#define NGT  256
#define NPR  8000
#define BATCH 512
#define NPOSMAX 128
#define NBUCKET 1024
#define BCAP 64              // max records per bucket (mean: bg ~7, fg ~0.8)
#define FG_CAP 192           // >= NPOSMAX + BCAP
#define BG_CAP 576           // >= BATCH + BCAP

// ---------------------------------------------------------------------------
// Threefry-2x32 (JAX default PRNG), 20 rounds.
// ---------------------------------------------------------------------------
__host__ __device__ __forceinline__ void threefry2x32(
    uint32_t k0, uint32_t k1, uint32_t x0, uint32_t x1,
    uint32_t& o0, uint32_t& o1)
{
    uint32_t ks0 = k0, ks1 = k1, ks2 = k0 ^ k1 ^ 0x1BD11BDAu;
    uint32_t a = x0 + ks0, b = x1 + ks1;
    const uint32_t rot[2][4] = {{13u,15u,26u,6u},{17u,29u,16u,24u}};
#pragma unroll
    for (int i = 0; i < 5; ++i) {
        const uint32_t* r = rot[i & 1];
#pragma unroll
        for (int q = 0; q < 4; ++q) {
            a += b;
            b = (b << r[q]) | (b >> (32u - r[q]));
            b ^= a;
        }
        uint32_t i1 = (uint32_t)(i + 1);
        uint32_t kA = (i % 3 == 0) ? ks1 : (i % 3 == 1) ? ks2 : ks0;
        uint32_t kB = (i % 3 == 0) ? ks2 : (i % 3 == 1) ? ks0 : ks1;
        a += kA;
        b += kB + i1;
    }
    o0 = a; o1 = b;
}

__host__ __device__ __forceinline__ float jax_uniform_from_bits(uint32_t bits) {
    uint32_t fb = (bits >> 9) | 0x3f800000u;
    float f;
#ifdef __CUDA_ARCH__
    f = __uint_as_float(fb);
#else
    union { uint32_t u; float f; } c; c.u = fb; f = c.f;
#endif
    return f - 1.0f;
}

struct ImgKeys {
    uint32_t v[NIMG][4];   // per image: k1 (2 words), k2 (2 words)
};

// ---------------------------------------------------------------------------
// Scratch (device globals — no allocation allowed).
// g_hist is all-zeros at module load; the select kernel restores it to zero
// every call, so every graph replay sees identical state.
// g_brec slots are gated by g_hist counts, so they need no clearing.
// Record layout (3 x float4 = 48B):
//   [0] = (u, bits(r), p.x, p.y)   [1] = (p.z, p.w, g.x, g.y)
//   [2] = (g.z, g.w, label_f, 0)
// ---------------------------------------------------------------------------
__device__ int    g_hist[NIMG * 2 * NBUCKET];
__device__ float4 g_brec[(size_t)NIMG * 2 * NBUCKET * BCAP * 3];

// Guarded argmax step. Skip-safe:
//   in <= rd(best*un) <= best*un (real)  =>  in/un <= best
//   => rn(in/un) <= best  =>  strict '>' cannot fire  => safe to skip.
// When taken: __fdiv_rn == reference's rounded quotient; first-max via
// strict '>'. Bit-identical to the reference update.
#define EVAL_G(best, bi, pz, pw, px, py, ap, g, ag, m)                       \
    do {                                                                     \
        float wx = fmaxf(__fsub_rn(fminf((g).z, (pz)), fmaxf((g).x, (px))), 0.0f); \
        float wy = fmaxf(__fsub_rn(fminf((g).w, (pw)), fmaxf((g).y, (py))), 0.0f); \
        float in = __fmul_rn(wx, wy);                                        \
        float un = __fsub_rn(__fadd_rn((ag), (ap)), in);                     \
        if (in > __fmul_rd((best), un)) {                                    \
            float iou = __fdiv_rn(in, un);                                   \
            if (iou > (best)) { (best) = iou; (bi) = (m); }                  \
        }                                                                    \
    } while (0)

// ---------------------------------------------------------------------------
// Kernel 1: IoU matching + full-payload bucketed records.
// 8-way GT split x FOUR proposals per thread: thread `sub` handles GT subset
// m = sub, sub+8, ... for proposals r_q = base + 32q + grp (q = 0..3).
// Each inner iteration loads sgt[m]/sag[m] ONCE and evaluates 4 independent
// proposals -> LDS per eval /4 and 4 independent dependency chains.
// First eval peeled (one exact division per proposal) so best >= 0 holds and
// the loop guard collapses to one rd-rounded multiply test (proof above).
// Tail block (props >= 8000) clamps r for compute and suppresses publish.
// Each valid proposal publishes exactly ONE record (proposal box, matched gt
// box, label, uniform score, index) into its pool's bucket array
// (bucket = floor(u*1024), slot = atomicAdd on the histogram).
// ---------------------------------------------------------------------------
__global__ void match_kernel(const float* __restrict__ gt,
                             const int*   __restrict__ gtc,
                             const float* __restrict__ pr,
                             ImgKeys keys)
{
    const int img  = blockIdx.y;
    const int tid  = threadIdx.x;          // 256 = 32 groups x 8 subs
    const int sub  = tid & 7;
    const int grp  = tid >> 3;             // 0..31
    const int base = blockIdx.x * 128;     // 63 blocks cover 8064 >= 8000

    const int r0 = base + grp;
    const int r1 = base + 32 + grp;
    const int r2 = base + 64 + grp;
    const int r3 = base + 96 + grp;
    const int c0 = min(r0, NPR - 1), c1 = min(r1, NPR - 1);
    const int c2 = min(r2, NPR - 1), c3 = min(r3, NPR - 1);

    __shared__ float4 sgt[NGT];
    __shared__ float  sag[NGT];
    __shared__ int    sgc[NGT];

    {
        float4 g = reinterpret_cast<const float4*>(gt)[img * NGT + tid];
        sgt[tid] = g;
        sag[tid] = __fmul_rn(__fsub_rn(g.z, g.x), __fsub_rn(g.w, g.y));
        sgc[tid] = gtc[img * NGT + tid];
    }
    __syncthreads();

    const float4* prb = reinterpret_cast<const float4*>(pr) + img * NPR;
    float4 p0 = prb[c0], p1 = prb[c1], p2 = prb[c2], p3 = prb[c3];
    const float ap0 = __fmul_rn(__fsub_rn(p0.z, p0.x), __fsub_rn(p0.w, p0.y));
    const float ap1 = __fmul_rn(__fsub_rn(p1.z, p1.x), __fsub_rn(p1.w, p1.y));
    const float ap2 = __fmul_rn(__fsub_rn(p2.z, p2.x), __fsub_rn(p2.w, p2.y));
    const float ap3 = __fmul_rn(__fsub_rn(p3.z, p3.x), __fsub_rn(p3.w, p3.y));

    float best0, best1, best2, best3;
    int   bi0 = sub, bi1 = sub, bi2 = sub, bi3 = sub;
    {   // peeled first eval (m = sub): unconditional exact divisions
        float4 g = sgt[sub];
        float ag = sag[sub];
#define PEEL(best, pz, pw, px, py, ap)                                        \
        {                                                                     \
            float wx = fmaxf(__fsub_rn(fminf(g.z, (pz)), fmaxf(g.x, (px))), 0.0f); \
            float wy = fmaxf(__fsub_rn(fminf(g.w, (pw)), fmaxf(g.y, (py))), 0.0f); \
            float in = __fmul_rn(wx, wy);                                     \
            best = __fdiv_rn(in, __fsub_rn(__fadd_rn(ag, (ap)), in));         \
        }
        PEEL(best0, p0.z, p0.w, p0.x, p0.y, ap0);
        PEEL(best1, p1.z, p1.w, p1.x, p1.y, ap1);
        PEEL(best2, p2.z, p2.w, p2.x, p2.y, ap2);
        PEEL(best3, p3.z, p3.w, p3.x, p3.y, ap3);
#undef PEEL
    }

#pragma unroll 31
    for (int i = 1; i < NGT / 8; ++i) {
        const int m = sub + 8 * i;
        float4 g = sgt[m];
        float ag = sag[m];
        EVAL_G(best0, bi0, p0.z, p0.w, p0.x, p0.y, ap0, g, ag, m);
        EVAL_G(best1, bi1, p1.z, p1.w, p1.x, p1.y, ap1, g, ag, m);
        EVAL_G(best2, bi2, p2.z, p2.w, p2.x, p2.y, ap2, g, ag, m);
        EVAL_G(best3, bi3, p3.z, p3.w, p3.x, p3.y, ap3, g, ag, m);
    }

    // Reduce across the 8 subs: (max value, min index) == sequential first-max
#pragma unroll
    for (int off = 1; off <= 4; off <<= 1) {
#define RED(best, bi)                                                        \
        {                                                                    \
            float ob = __shfl_xor_sync(0xffffffffu, best, off);              \
            int  obi = __shfl_xor_sync(0xffffffffu, bi,   off);              \
            if (ob > best || (ob == best && obi < bi)) { best = ob; bi = obi; } \
        }
        RED(best0, bi0); RED(best1, bi1); RED(best2, bi2); RED(best3, bi3);
#undef RED
    }

    // Publish: sub q (q = 0..3) owns proposal q. FG_IOU == BG_IOU == 0.5.
    if (sub < 4) {
        const int   myR  = base + 32 * sub + grp;
        float  bb; int bib; float4 pb; float apq;
        if      (sub == 0) { bb = best0; bib = bi0; pb = p0; apq = ap0; }
        else if (sub == 1) { bb = best1; bib = bi1; pb = p1; apq = ap1; }
        else if (sub == 2) { bb = best2; bib = bi2; pb = p2; apq = ap2; }
        else               { bb = best3; bib = bi3; pb = p3; apq = ap3; }
        (void)apq;

        if (myR < NPR) {
            const bool fg = (bb >= 0.5f);
            const int pool = fg ? 0 : 1;
            const uint32_t* kv = keys.v[img];
            uint32_t kk0 = fg ? kv[0] : kv[2];
            uint32_t kk1 = fg ? kv[1] : kv[3];
            uint32_t w0, w1;
            threefry2x32(kk0, kk1, 0u, (uint32_t)myR, w0, w1);
            float u = jax_uniform_from_bits(w0 ^ w1);

            int bkt = (int)(u * (float)NBUCKET);
            int hidx = (img * 2 + pool) * NBUCKET + bkt;
            int pos = atomicAdd(&g_hist[hidx], 1);
            if (pos < BCAP) {
                float4 gb = sgt[bib];
                float  lab = fg ? (float)sgc[bib] : 0.0f;
                float4* rp = &g_brec[((size_t)hidx * BCAP + pos) * 3];
                rp[0] = make_float4(u, __int_as_float(myR), pb.x, pb.y);
                rp[1] = make_float4(pb.z, pb.w, gb.x, gb.y);
                rp[2] = make_float4(gb.z, gb.w, lab, 0.0f);
            }
        }
    }
}

// ---------------------------------------------------------------------------
// Kernel 2 (payload-carrying select): per-image fg/bg selection CONCURRENTLY
// (warps 0-15 = fg, warps 16-31 = bg, named barriers within half, one
// __syncthreads to publish the fg total to the bg half).
//
//  1. load precomputed 1024-bucket histogram (+ reset to zero for replay)
//  2. prefix sums -> cumE[] (exclusive), threshold bucket B (cum >= target)
//  3. candidate slot i -> bucket via SMEM binary search on cumE; fetch the
//     48B record with 3 independent LDG.128 (one parallel round trip);
//     key goes to SMEM, record stays in registers
//  4. exact rank = cumE[bucket] + #(same-bucket keys < k); keys are unique
//     u64 (score,index) -> total order -> rank bijection == stable argsort
//     prefix, independent of the nondeterministic within-bucket atomic
//     order; ranked threads write the output row DIRECTLY from registers.
//     bg half also writes the padding rows (zero boxes, cls -1).
// ---------------------------------------------------------------------------
#define NB() asm volatile("bar.sync %0, %1;" :: "r"(half + 1), "r"(512) : "memory")

__global__ void select_gather_kernel(float* __restrict__ out)
{
    __shared__ unsigned long long skey_fg[FG_CAP];
    __shared__ unsigned long long skey_bg[BG_CAP];
    __shared__ int cumE2[2][NBUCKET + 1];
    __shared__ int wsum2[2][16];
    __shared__ int bidx[2];
    __shared__ int totals[2];

    const int img  = blockIdx.x;
    const int tid  = threadIdx.x;  // 1024
    const int half = tid >> 9;     // 0 = fg, 1 = bg
    const int ht   = tid & 511;
    const int lane = tid & 31;
    const int hw   = ht >> 5;      // warp within half, 0..15

    const int target = half ? BATCH : NPOSMAX;
    const int cap    = half ? BG_CAP : FG_CAP;
    unsigned long long* skey = half ? skey_bg : skey_fg;
    int* cumE = cumE2[half];
    int* hist = &g_hist[(img * 2 + half) * NBUCKET];
    const float4* bsrc = &g_brec[(size_t)(img * 2 + half) * NBUCKET * BCAP * 3];

    if (ht == 0) bidx[half] = NBUCKET - 1;

    // Phase 1: load histogram from global, reset it for the next replay
    const int v0 = hist[2 * ht];
    const int v1 = hist[2 * ht + 1];
    hist[2 * ht]     = 0;
    hist[2 * ht + 1] = 0;

    // Phase 2: scan (each thread owns buckets 2ht, 2ht+1)
    int v = v0 + v1;
#pragma unroll
    for (int off = 1; off < 32; off <<= 1) {
        int o = __shfl_up_sync(0xffffffffu, v, off);
        if (lane >= off) v += o;
    }
    if (lane == 31) wsum2[half][hw] = v;
    NB();
    if (ht < 32) {
        int w = (lane < 16) ? wsum2[half][lane] : 0;
#pragma unroll
        for (int off = 1; off < 32; off <<= 1) {
            int o = __shfl_up_sync(0xffffffffu, w, off);
            if (lane >= off) w += o;
        }
        if (lane < 16) wsum2[half][lane] = w;
    }
    NB();
    const int incl  = v + (hw ? wsum2[half][hw - 1] : 0);  // incl cum @ 2ht+1
    const int excl1 = incl - v1;                            // excl cum @ 2ht+1
    const int excl0 = excl1 - v0;                           // excl cum @ 2ht
    cumE[2 * ht]     = excl0;
    cumE[2 * ht + 1] = excl1;
    if (ht == 511) { cumE[NBUCKET] = incl; totals[half] = incl; }
    // threshold bucket: unique b with excl < target <= incl
    if (excl0 < target && excl0 + v0 >= target) bidx[half] = 2 * ht;
    if (excl1 < target && incl >= target)       bidx[half] = 2 * ht + 1;
    __syncthreads();   // join halves once: bg needs totals[0]
    const int B = bidx[half];
    const int cnt = min(cumE[B + 1], cap);

    // Phase 3: fetch records — slot -> bucket via binary search on cumE
    float4 recA[2][3];
    int    rb[2];
    bool   rv[2] = {false, false};
#pragma unroll
    for (int q = 0; q < 2; ++q) {
        int i = ht + q * 512;
        if (i < cnt) {
            int lo = 0, hi2 = B;
            while (lo < hi2) {
                int mid = (lo + hi2 + 1) >> 1;
                if (cumE[mid] <= i) lo = mid; else hi2 = mid - 1;
            }
            int b = lo;
            int j = i - cumE[b];
            if (j < BCAP) {
                const float4* rp = bsrc + ((size_t)b * BCAP + j) * 3;
                recA[q][0] = rp[0];
                recA[q][1] = rp[1];
                recA[q][2] = rp[2];
                rb[q] = b;
                rv[q] = true;
                unsigned long long k =
                    (((unsigned long long)__float_as_uint(recA[q][0].x)) << 32)
                    | __float_as_uint(recA[q][0].y);
                skey[i] = k;
            }
        }
    }
    NB();

    // Phase 4: exact rank + direct output write
    const int np = min(totals[0], NPOSMAX);
    const int nn = min(totals[1], BATCH - np);

#pragma unroll
    for (int q = 0; q < 2; ++q) {
        if (!rv[q]) continue;
        int i = ht + q * 512;
        unsigned long long k = skey[i];
        int b   = rb[q];
        int lo  = cumE[b];
        int hiE = min(cumE[b + 1], cnt);
        int rank = lo;
        for (int j = lo; j < hiE; ++j)
            rank += (skey[j] < k);

        int slot = -1;
        if (half == 0) { if (rank < np) slot = rank; }
        else           { if (rank < nn) slot = np + rank; }
        if (slot >= 0) {
            float* ob = out + (size_t)(img * BATCH + slot) * 8;
            float4 rA = recA[q][0], rB = recA[q][1], rC = recA[q][2];
            ob[0] = rA.z; ob[1] = rA.w; ob[2] = rB.x; ob[3] = rB.y;
            ob[4] = rB.z; ob[5] = rB.w; ob[6] = rC.x; ob[7] = rC.y;
            out[(size_t)NIMG * BATCH * 8 + img * BATCH + slot] = rC.z;
        }
    }

    // Padding rows (bg half): zero boxes, cls -1
    if (half == 1) {
        for (int slot = np + nn + ht; slot < BATCH; slot += 512) {
            float* ob = out + (size_t)(img * BATCH + slot) * 8;
#pragma unroll
            for (int e = 0; e < 8; ++e) ob[e] = 0.0f;
            out[(size_t)NIMG * BATCH * 8 + img * BATCH + slot] = -1.0f;
        }
    }
}

// ---------------------------------------------------------------------------
// Host: per-image (k1, k2) Threefry keys, partitionable mode:
//   root = key(42) = (0, 42)
//   keys[i]  = TF(root, (0, i))
//   k1, k2   = TF(keys[i], (0,0)), TF(keys[i], (0,1))
// ---------------------------------------------------------------------------
static void compute_keys(ImgKeys& out)
{
    for (int i = 0; i < NIMG; ++i) {
        uint32_t ik0, ik1;
        threefry2x32(0u, 42u, 0u, (uint32_t)i, ik0, ik1);
        uint32_t a0, a1, b0, b1;
        threefry2x32(ik0, ik1, 0u, 0u, a0, a1);   // k1
        threefry2x32(ik0, ik1, 0u, 1u, b0, b1);   // k2
        out.v[i][0] = a0; out.v[i][1] = a1;
        out.v[i][2] = b0; out.v[i][3] = b1;
    }
}

extern "C" void kernel_launch(void* const* d_in, const int* in_sizes, int n_in,
                              void* d_out, int out_size)
{
    const float* gt  = (const float*)d_in[0];  // [8,256,4]
    const int*   gtc = (const int*)  d_in[1];  // [8,256]
    const float* pr  = (const float*)d_in[2];  // [8,8000,4]
    float* out = (float*)d_out;

    (void)in_sizes; (void)n_in; (void)out_size;

    ImgKeys keys;
    compute_keys(keys);

    dim3 g1((NPR + 127) / 128, NIMG);      // 63 x 8 blocks, 256 thr each
    match_kernel<<<g1, 256>>>(gt, gtc, pr, keys);
    select_gather_kernel<<<NIMG, 1024>>>(out);
}

// round 16
// speedup vs baseline: 1.0839x; 1.0839x over previous
#include <cuda_runtime.h>
#include <cuda_bf16.h>
#include <cstdint>

// Problem constants
#define NIMG 8
#define NGT  256
#define NPR  8000
#define BATCH 512
#define NPOSMAX 128
#define NBUCKET 1024
#define BCAP 64              // max records per bucket (mean: bg ~7, fg ~0.8)
#define FG_CAP 192           // >= NPOSMAX + BCAP
#define BG_CAP 576           // >= BATCH + BCAP

// ---------------------------------------------------------------------------
// Threefry-2x32 (JAX default PRNG), 20 rounds.
// ---------------------------------------------------------------------------
__host__ __device__ __forceinline__ void threefry2x32(
    uint32_t k0, uint32_t k1, uint32_t x0, uint32_t x1,
    uint32_t& o0, uint32_t& o1)
{
    uint32_t ks0 = k0, ks1 = k1, ks2 = k0 ^ k1 ^ 0x1BD11BDAu;
    uint32_t a = x0 + ks0, b = x1 + ks1;
    const uint32_t rot[2][4] = {{13u,15u,26u,6u},{17u,29u,16u,24u}};
#pragma unroll
    for (int i = 0; i < 5; ++i) {
        const uint32_t* r = rot[i & 1];
#pragma unroll
        for (int q = 0; q < 4; ++q) {
            a += b;
            b = (b << r[q]) | (b >> (32u - r[q]));
            b ^= a;
        }
        uint32_t i1 = (uint32_t)(i + 1);
        uint32_t kA = (i % 3 == 0) ? ks1 : (i % 3 == 1) ? ks2 : ks0;
        uint32_t kB = (i % 3 == 0) ? ks2 : (i % 3 == 1) ? ks0 : ks1;
        a += kA;
        b += kB + i1;
    }
    o0 = a; o1 = b;
}

__host__ __device__ __forceinline__ float jax_uniform_from_bits(uint32_t bits) {
    uint32_t fb = (bits >> 9) | 0x3f800000u;
    float f;
#ifdef __CUDA_ARCH__
    f = __uint_as_float(fb);
#else
    union { uint32_t u; float f; } c; c.u = fb; f = c.f;
#endif
    return f - 1.0f;
}

struct ImgKeys {
    uint32_t v[NIMG][4];   // per image: k1 (2 words), k2 (2 words)
};

// ---------------------------------------------------------------------------
// Scratch (device globals — no allocation allowed).
// g_hist is all-zeros at module load; the select kernel restores it to zero
// every call, so every graph replay sees identical state.
// g_brec slots are gated by g_hist counts, so they need no clearing.
// Record layout (3 x float4 = 48B):
//   [0] = (u, bits(r), p.x, p.y)   [1] = (p.z, p.w, g.x, g.y)
//   [2] = (g.z, g.w, label_f, 0)
// ---------------------------------------------------------------------------
__device__ int    g_hist[NIMG * 2 * NBUCKET];
__device__ float4 g_brec[(size_t)NIMG * 2 * NBUCKET * BCAP * 3];

// Guarded argmax step with a forced branch around the division.
// Skip-safe: in <= rd(best*un) <= best*un (real)  =>  in/un <= best
// => rn(in/un) <= best (best representable)  =>  strict '>' cannot fire.
// When taken: q = div.rn == reference's rounded quotient; first-max via
// strict '>'. Bit-identical to the reference update.
#define EVAL_GUARDED(best, bi, in, un, m)                                \
    do {                                                                 \
        float _thr = __fmul_rd((best), (un));                            \
        asm("{\n\t"                                                     \
            ".reg .pred p;\n\t"                                        \
            ".reg .f32 q;\n\t"                                         \
            "setp.gt.f32 p, %2, %3;\n\t"                               \
            "@!p bra DONE%=;\n\t"                                       \
            "div.rn.f32 q, %2, %4;\n\t"                                 \
            "setp.gt.f32 p, q, %0;\n\t"                                 \
            "@p mov.f32 %0, q;\n\t"                                     \
            "@p mov.s32 %1, %5;\n\t"                                    \
            "DONE%=:\n\t"                                               \
            "}"                                                          \
            : "+f"(best), "+r"(bi)                                      \
            : "f"(in), "f"(_thr), "f"(un), "r"(m));                     \
    } while (0)

// ---------------------------------------------------------------------------
// Kernel 1: IoU matching + full-payload bucketed records.
// 8 threads per proposal-pair lane-group; thread `sub` handles GT subset
// m = sub, sub+8, ... for TWO proposals (r0, r1 = r0+32). 8000 = 125*64 so
// there are no bounds checks. First eval peeled (one exact division) so the
// loop invariant is best >= 0; the loop body uses EVAL_GUARDED.
// Each proposal publishes exactly ONE record (proposal box, matched gt box,
// label, uniform score, index) into its pool's bucket array
// (bucket = floor(u*1024), slot = atomicAdd on the histogram).
// PDL: triggers the dependent launch immediately (data safety comes from the
// consumer's cudaGridDependencySynchronize, which waits for full completion).
// ---------------------------------------------------------------------------
__global__ void match_kernel(const float* __restrict__ gt,
                             const int*   __restrict__ gtc,
                             const float* __restrict__ pr,
                             ImgKeys keys)
{
#if __CUDA_ARCH__ >= 900
    cudaTriggerProgrammaticLaunchCompletion();
#endif
    const int img = blockIdx.y;
    const int tid = threadIdx.x;           // 256 threads = 32 pairs x 8 subs
    const int sub = tid & 7;
    const int pid = tid >> 3;              // 0..31
    const int base = blockIdx.x * 64;      // 125 blocks x 64 proposals = 8000
    const int r0 = base + pid;
    const int r1 = base + 32 + pid;

    __shared__ float4 sgt[NGT];
    __shared__ float  sag[NGT];
    __shared__ int    sgc[NGT];

    {
        float4 g = reinterpret_cast<const float4*>(gt)[img * NGT + tid];
        sgt[tid] = g;
        sag[tid] = __fmul_rn(__fsub_rn(g.z, g.x), __fsub_rn(g.w, g.y));
        sgc[tid] = gtc[img * NGT + tid];
    }
    __syncthreads();

    float4 p0 = reinterpret_cast<const float4*>(pr)[img * NPR + r0];
    float4 p1 = reinterpret_cast<const float4*>(pr)[img * NPR + r1];
    const float ap0 = __fmul_rn(__fsub_rn(p0.z, p0.x), __fsub_rn(p0.w, p0.y));
    const float ap1 = __fmul_rn(__fsub_rn(p1.z, p1.x), __fsub_rn(p1.w, p1.y));

    float best0, best1;
    int   bi0 = sub, bi1 = sub;
    {   // peeled first eval (m = sub): unconditional exact division
        float4 g = sgt[sub];
        float ag = sag[sub];
        float wx0 = fmaxf(__fsub_rn(fminf(g.z, p0.z), fmaxf(g.x, p0.x)), 0.0f);
        float wy0 = fmaxf(__fsub_rn(fminf(g.w, p0.w), fmaxf(g.y, p0.y)), 0.0f);
        float in0 = __fmul_rn(wx0, wy0);
        best0 = __fdiv_rn(in0, __fsub_rn(__fadd_rn(ag, ap0), in0));
        float wx1 = fmaxf(__fsub_rn(fminf(g.z, p1.z), fmaxf(g.x, p1.x)), 0.0f);
        float wy1 = fmaxf(__fsub_rn(fminf(g.w, p1.w), fmaxf(g.y, p1.y)), 0.0f);
        float in1 = __fmul_rn(wx1, wy1);
        best1 = __fdiv_rn(in1, __fsub_rn(__fadd_rn(ag, ap1), in1));
    }

#pragma unroll 31
    for (int i = 1; i < NGT / 8; ++i) {
        const int m = sub + 8 * i;
        float4 g = sgt[m];
        float ag = sag[m];

        float wx0 = fmaxf(__fsub_rn(fminf(g.z, p0.z), fmaxf(g.x, p0.x)), 0.0f);
        float wy0 = fmaxf(__fsub_rn(fminf(g.w, p0.w), fmaxf(g.y, p0.y)), 0.0f);
        float in0 = __fmul_rn(wx0, wy0);
        float un0 = __fsub_rn(__fadd_rn(ag, ap0), in0);
        EVAL_GUARDED(best0, bi0, in0, un0, m);

        float wx1 = fmaxf(__fsub_rn(fminf(g.z, p1.z), fmaxf(g.x, p1.x)), 0.0f);
        float wy1 = fmaxf(__fsub_rn(fminf(g.w, p1.w), fmaxf(g.y, p1.y)), 0.0f);
        float in1 = __fmul_rn(wx1, wy1);
        float un1 = __fsub_rn(__fadd_rn(ag, ap1), in1);
        EVAL_GUARDED(best1, bi1, in1, un1, m);
    }

    // Reduce across the 8 subs: (max value, min index) == sequential first-max
#pragma unroll
    for (int off = 1; off <= 4; off <<= 1) {
        float ob = __shfl_xor_sync(0xffffffffu, best0, off);
        int  obi = __shfl_xor_sync(0xffffffffu, bi0,   off);
        if (ob > best0 || (ob == best0 && obi < bi0)) { best0 = ob; bi0 = obi; }
        ob  = __shfl_xor_sync(0xffffffffu, best1, off);
        obi = __shfl_xor_sync(0xffffffffu, bi1,   off);
        if (ob > best1 || (ob == best1 && obi < bi1)) { best1 = ob; bi1 = obi; }
    }

    const bool fg0 = (best0 >= 0.5f);      // FG_IOU == BG_IOU == 0.5
    const bool fg1 = (best1 >= 0.5f);

    // Converged Threefry (subs 4-7 duplicate subs 0-3; only subs 0-3 publish):
    //   sub&3==0: (k1, r0)  1: (k1, r1)  2: (k2, r0)  3: (k2, r1)
    const uint32_t* kv = keys.v[img];
    uint32_t kk0 = (sub & 2) ? kv[2] : kv[0];
    uint32_t kk1 = (sub & 2) ? kv[3] : kv[1];
    const int  myR  = (sub & 1) ? r1 : r0;
    const bool myFg = (sub & 1) ? fg1 : fg0;
    const int  pool = (sub & 2) >> 1;          // 0 = fg draw, 1 = bg draw
    uint32_t w0, w1;
    threefry2x32(kk0, kk1, 0u, (uint32_t)myR, w0, w1);
    float u = jax_uniform_from_bits(w0 ^ w1);

    const bool publish = (sub < 4) && (pool == 0 ? myFg : !myFg);
    if (publish) {
        int bkt = (int)(u * (float)NBUCKET);
        int hidx = (img * 2 + pool) * NBUCKET + bkt;
        int pos = atomicAdd(&g_hist[hidx], 1);
        if (pos < BCAP) {
            float4 pb = (sub & 1) ? p1 : p0;
            int    bi = (sub & 1) ? bi1 : bi0;
            float4 gb = sgt[bi];
            float  lab = (pool == 0) ? (float)sgc[bi] : 0.0f;
            float4* rp = &g_brec[((size_t)hidx * BCAP + pos) * 3];
            rp[0] = make_float4(u, __int_as_float(myR), pb.x, pb.y);
            rp[1] = make_float4(pb.z, pb.w, gb.x, gb.y);
            rp[2] = make_float4(gb.z, gb.w, lab, 0.0f);
        }
    }
}

// ---------------------------------------------------------------------------
// Kernel 2 (payload-carrying select, PDL consumer): per-image fg/bg selection
// CONCURRENTLY (warps 0-15 = fg, warps 16-31 = bg, named barriers within
// half, one __syncthreads to publish the fg total to the bg half).
// Launched with programmatic stream serialization: the grid is resident and
// waiting in cudaGridDependencySynchronize while match drains, so the
// inter-kernel launch gap disappears.
//
//  1. load precomputed 1024-bucket histogram (int2) (+ reset for replay)
//  2. prefix sums -> cumE[] (exclusive), threshold bucket B (cum >= target)
//  3. candidate slot i -> bucket via SMEM binary search on cumE; fetch the
//     48B record with 3 independent LDG.128 (one parallel round trip);
//     key goes to SMEM, record stays in registers
//  4. exact rank = cumE[bucket] + #(same-bucket keys < k); keys are unique
//     u64 (score,index) -> total order -> rank bijection == stable argsort
//     prefix, independent of the nondeterministic within-bucket atomic
//     order; ranked threads write the output row DIRECTLY from registers.
//     bg half also writes the padding rows (zero boxes, cls -1).
// ---------------------------------------------------------------------------
#define NB() asm volatile("bar.sync %0, %1;" :: "r"(half + 1), "r"(512) : "memory")

__global__ void select_gather_kernel(float* __restrict__ out)
{
#if __CUDA_ARCH__ >= 900
    cudaGridDependencySynchronize();
#endif
    __shared__ unsigned long long skey_fg[FG_CAP];
    __shared__ unsigned long long skey_bg[BG_CAP];
    __shared__ int cumE2[2][NBUCKET + 1];
    __shared__ int wsum2[2][16];
    __shared__ int bidx[2];
    __shared__ int totals[2];

    const int img  = blockIdx.x;
    const int tid  = threadIdx.x;  // 1024
    const int half = tid >> 9;     // 0 = fg, 1 = bg
    const int ht   = tid & 511;
    const int lane = tid & 31;
    const int hw   = ht >> 5;      // warp within half, 0..15

    const int target = half ? BATCH : NPOSMAX;
    const int cap    = half ? BG_CAP : FG_CAP;
    unsigned long long* skey = half ? skey_bg : skey_fg;
    int* cumE = cumE2[half];
    int* hist = &g_hist[(img * 2 + half) * NBUCKET];
    const float4* bsrc = &g_brec[(size_t)(img * 2 + half) * NBUCKET * BCAP * 3];

    if (ht == 0) bidx[half] = NBUCKET - 1;

    // Phase 1: load histogram (vectorized), reset it for the next replay
    int2 hv = reinterpret_cast<int2*>(hist)[ht];
    reinterpret_cast<int2*>(hist)[ht] = make_int2(0, 0);
    const int v0 = hv.x;
    const int v1 = hv.y;

    // Phase 2: scan (each thread owns buckets 2ht, 2ht+1)
    int v = v0 + v1;
#pragma unroll
    for (int off = 1; off < 32; off <<= 1) {
        int o = __shfl_up_sync(0xffffffffu, v, off);
        if (lane >= off) v += o;
    }
    if (lane == 31) wsum2[half][hw] = v;
    NB();
    if (ht < 32) {
        int w = (lane < 16) ? wsum2[half][lane] : 0;
#pragma unroll
        for (int off = 1; off < 32; off <<= 1) {
            int o = __shfl_up_sync(0xffffffffu, w, off);
            if (lane >= off) w += o;
        }
        if (lane < 16) wsum2[half][lane] = w;
    }
    NB();
    const int incl  = v + (hw ? wsum2[half][hw - 1] : 0);  // incl cum @ 2ht+1
    const int excl1 = incl - v1;                            // excl cum @ 2ht+1
    const int excl0 = excl1 - v0;                           // excl cum @ 2ht
    cumE[2 * ht]     = excl0;
    cumE[2 * ht + 1] = excl1;
    if (ht == 511) { cumE[NBUCKET] = incl; totals[half] = incl; }
    // threshold bucket: unique b with excl < target <= incl
    if (excl0 < target && excl0 + v0 >= target) bidx[half] = 2 * ht;
    if (excl1 < target && incl >= target)       bidx[half] = 2 * ht + 1;
    __syncthreads();   // join halves once: bg needs totals[0]
    const int B = bidx[half];
    const int cnt = min(cumE[B + 1], cap);

    // Phase 3: fetch records — slot -> bucket via binary search on cumE
    float4 recA[2][3];
    int    rb[2];
    bool   rv[2] = {false, false};
#pragma unroll
    for (int q = 0; q < 2; ++q) {
        int i = ht + q * 512;
        if (i < cnt) {
            int lo = 0, hi2 = B;
            while (lo < hi2) {
                int mid = (lo + hi2 + 1) >> 1;
                if (cumE[mid] <= i) lo = mid; else hi2 = mid - 1;
            }
            int b = lo;
            int j = i - cumE[b];
            if (j < BCAP) {
                const float4* rp = bsrc + ((size_t)b * BCAP + j) * 3;
                recA[q][0] = rp[0];
                recA[q][1] = rp[1];
                recA[q][2] = rp[2];
                rb[q] = b;
                rv[q] = true;
                unsigned long long k =
                    (((unsigned long long)__float_as_uint(recA[q][0].x)) << 32)
                    | __float_as_uint(recA[q][0].y);
                skey[i] = k;
            }
        }
    }
    NB();

    // Phase 4: exact rank + direct output write
    const int np = min(totals[0], NPOSMAX);
    const int nn = min(totals[1], BATCH - np);

#pragma unroll
    for (int q = 0; q < 2; ++q) {
        if (!rv[q]) continue;
        int i = ht + q * 512;
        unsigned long long k = skey[i];
        int b   = rb[q];
        int lo  = cumE[b];
        int hiE = min(cumE[b + 1], cnt);
        int rank = lo;
        for (int j = lo; j < hiE; ++j)
            rank += (skey[j] < k);

        int slot = -1;
        if (half == 0) { if (rank < np) slot = rank; }
        else           { if (rank < nn) slot = np + rank; }
        if (slot >= 0) {
            float* ob = out + (size_t)(img * BATCH + slot) * 8;
            float4 rA = recA[q][0], rB = recA[q][1], rC = recA[q][2];
            ob[0] = rA.z; ob[1] = rA.w; ob[2] = rB.x; ob[3] = rB.y;
            ob[4] = rB.z; ob[5] = rB.w; ob[6] = rC.x; ob[7] = rC.y;
            out[(size_t)NIMG * BATCH * 8 + img * BATCH + slot] = rC.z;
        }
    }

    // Padding rows (bg half): zero boxes, cls -1
    if (half == 1) {
        for (int slot = np + nn + ht; slot < BATCH; slot += 512) {
            float* ob = out + (size_t)(img * BATCH + slot) * 8;
#pragma unroll
            for (int e = 0; e < 8; ++e) ob[e] = 0.0f;
            out[(size_t)NIMG * BATCH * 8 + img * BATCH + slot] = -1.0f;
        }
    }
}

// ---------------------------------------------------------------------------
// Host: per-image (k1, k2) Threefry keys, partitionable mode:
//   root = key(42) = (0, 42)
//   keys[i]  = TF(root, (0, i))
//   k1, k2   = TF(keys[i], (0,0)), TF(keys[i], (0,1))
// ---------------------------------------------------------------------------
static void compute_keys(ImgKeys& out)
{
    for (int i = 0; i < NIMG; ++i) {
        uint32_t ik0, ik1;
        threefry2x32(0u, 42u, 0u, (uint32_t)i, ik0, ik1);
        uint32_t a0, a1, b0, b1;
        threefry2x32(ik0, ik1, 0u, 0u, a0, a1);   // k1
        threefry2x32(ik0, ik1, 0u, 1u, b0, b1);   // k2
        out.v[i][0] = a0; out.v[i][1] = a1;
        out.v[i][2] = b0; out.v[i][3] = b1;
    }
}

extern "C" void kernel_launch(void* const* d_in, const int* in_sizes, int n_in,
                              void* d_out, int out_size)
{
    const float* gt  = (const float*)d_in[0];  // [8,256,4]
    const int*   gtc = (const int*)  d_in[1];  // [8,256]
    const float* pr  = (const float*)d_in[2];  // [8,8000,4]
    float* out = (float*)d_out;

    (void)in_sizes; (void)n_in; (void)out_size;

    ImgKeys keys;
    compute_keys(keys);

    dim3 g1(NPR / 64, NIMG);               // 125 x 8 blocks, 256 thr each
    match_kernel<<<g1, 256>>>(gt, gtc, pr, keys);

    // PDL launch of the dependent select kernel (hides the launch gap).
    cudaLaunchConfig_t cfg = {};
    cfg.gridDim  = dim3(NIMG, 1, 1);
    cfg.blockDim = dim3(1024, 1, 1);
    cfg.dynamicSmemBytes = 0;
    cfg.stream = 0;
    cudaLaunchAttribute attrs[1];
    attrs[0].id = cudaLaunchAttributeProgrammaticStreamSerialization;
    attrs[0].val.programmaticStreamSerializationAllowed = 1;
    cfg.attrs = attrs;
    cfg.numAttrs = 1;
    cudaLaunchKernelEx(&cfg, select_gather_kernel, out);
}